// round 16
// baseline (speedup 1.0000x reference)
#include <cuda_runtime.h>
#include <cuda_fp16.h>
#include <cstdint>
#include <cstddef>

#define MROWS   8192
#define NOUT    1024
#define CHUNK   8388608
#define SLOPE   0.2f
#define EPSV    1e-5f

#define NSTAGE  4
#define GEMM_SMEM (NSTAGE * 1024 * 16)   // 64 KB dynamic smem per CTA

// ---------------------------------------------------------------------------
// Scratch (device globals)
// ---------------------------------------------------------------------------
__device__ __half g_ybufh[4u * MROWS * NOUT]; // 64 MB: branch GEMM outputs (fp16)
__device__ __half g_yfh[MROWS * NOUT];        // 16 MB: final GEMM output (fp16)
__device__ uint4  g_abuf[983040];             // branch A' fp16 fragment-major
__device__ uint4  g_accf[1048576];            // stage-5 A' fp16 fragment-major
__device__ uint4  g_wbuf[253952];             // W' fp16 fragment-major (all 5)
__device__ int    g_rows[4 * MROWS];
__device__ float  g_stats[5 * 2 * NOUT];      // raw [sum|sumsq] -> [scale|shift]

// Cached side-streams/events (infra only; captured work identical per call)
static cudaStream_t g_s2 = nullptr, g_s3 = nullptr;
static cudaEvent_t  g_e1 = nullptr, g_e2 = nullptr, g_e3 = nullptr;
static cudaEvent_t  g_e4 = nullptr, g_e6 = nullptr;

// ---------------------------------------------------------------------------
// Helpers
// ---------------------------------------------------------------------------
__device__ __forceinline__ uint32_t smem_u32(const void* p) {
    uint32_t a;
    asm("{ .reg .u64 t; cvta.to.shared.u64 t, %1; cvt.u32.u64 %0, t; }" : "=r"(a) : "l"(p));
    return a;
}
__device__ __forceinline__ uint32_t h2pack(float a, float b) {
    __half2 h = __floats2half2_rn(a, b);
    return *(uint32_t*)&h;
}
__device__ __forceinline__ float4 h4unpack(uint2 v) {
    __half2 a = *(__half2*)&v.x, b = *(__half2*)&v.y;
    float2 fa = __half22float2(a), fb = __half22float2(b);
    return make_float4(fa.x, fa.y, fb.x, fb.y);
}
__device__ __forceinline__ void mma_f16(float c[4], const uint4& a, uint32_t b0, uint32_t b1)
{
    asm volatile(
        "mma.sync.aligned.m16n8k16.row.col.f32.f16.f16.f32 "
        "{%0,%1,%2,%3}, {%4,%5,%6,%7}, {%8,%9}, {%0,%1,%2,%3};\n"
        : "+f"(c[0]), "+f"(c[1]), "+f"(c[2]), "+f"(c[3])
        : "r"(a.x), "r"(a.y), "r"(a.z), "r"(a.w), "r"(b0), "r"(b1));
}
__device__ __forceinline__ float leaky(float v) { return v >= 0.f ? v : SLOPE * v; }

// ---------------------------------------------------------------------------
// Index chains
// ---------------------------------------------------------------------------
__global__ void idx_kernel(const int* __restrict__ F0, const int* __restrict__ F1,
                           const int* __restrict__ F2, const int* __restrict__ F3,
                           int* __restrict__ rows)
{
    int i = blockIdx.x * blockDim.x + threadIdx.x;
    if (i >= MROWS) return;
    int b  = i >> 7;
    int i3 = F3[i];
    int i2 = F2[(b << 8) + i3];
    int i1 = F1[(b << 9) + i2];
    int i0 = F0[(b << 10) + i1];
    rows[0 * MROWS + i] = (b << 11) + i0;
    rows[1 * MROWS + i] = (b << 10) + i1;
    rows[2 * MROWS + i] = (b << 9)  + i2;
    rows[3 * MROWS + i] = (b << 8)  + i3;
}

// ---------------------------------------------------------------------------
// Gather + fp16-convert branch A operands into m16n8k16 fragment-major layout.
// ---------------------------------------------------------------------------
__global__ void gatherA_kernel(const float* __restrict__ f0, const float* __restrict__ f1,
                               const float* __restrict__ f2, const float* __restrict__ f3,
                               const int* __restrict__ rows, uint4* __restrict__ out)
{
    int v = blockIdx.x * 256 + threadIdx.x;   // 0 .. 983039
    int s, base, lognch;
    if      (v < 65536)  { s = 0; base = 0;      lognch = 1; }
    else if (v < 196608) { s = 1; base = 65536;  lognch = 2; }
    else if (v < 458752) { s = 2; base = 196608; lognch = 3; }
    else                 { s = 3; base = 458752; lognch = 4; }
    const float* X = s == 0 ? f0 : s == 1 ? f1 : s == 2 ? f2 : f3;
    const int K = 32 << lognch;
    int lv = v - base;
    int lane = lv & 31, f = (lv >> 5) & 7, wm = (lv >> 8) & 1;
    int mt = f >> 1, ks = f & 1;
    int rest = lv >> 9;
    int kc   = rest & ((1 << lognch) - 1);
    int mblk = rest >> lognch;
    int lg = lane >> 2, lt = lane & 3;
    int gR = mblk * 128 + wm * 64 + mt * 16 + lg;
    const int* rs = rows + s * MROWS;
    int r0 = rs[gR], r1 = rs[gR + 8];
    int c0 = kc * 32 + ks * 16 + lt * 2;
    const float* p0 = X + (size_t)r0 * K + c0;
    const float* p1 = X + (size_t)r1 * K + c0;
    float2 a0 = *(const float2*)p0,       a1 = *(const float2*)p1;
    float2 a2 = *(const float2*)(p0 + 8), a3 = *(const float2*)(p1 + 8);
    uint4 o;
    o.x = h2pack(a0.x, a0.y);
    o.y = h2pack(a1.x, a1.y);
    o.z = h2pack(a2.x, a2.y);
    o.w = h2pack(a3.x, a3.y);
    out[v] = o;
}

// ---------------------------------------------------------------------------
// Convert all 5 weight matrices into fp16 fragment-major B layout.
// ---------------------------------------------------------------------------
__global__ void convW_kernel(const float* __restrict__ w0, const float* __restrict__ w1,
                             const float* __restrict__ w2, const float* __restrict__ w3,
                             const float* __restrict__ w4, uint4* __restrict__ out)
{
    int v = blockIdx.x * 256 + threadIdx.x;   // 0 .. 253951
    int s, base, lognch;
    if      (v < 8192)   { s = 0; base = 0;      lognch = 1; }
    else if (v < 24576)  { s = 1; base = 8192;   lognch = 2; }
    else if (v < 57344)  { s = 2; base = 24576;  lognch = 3; }
    else if (v < 122880) { s = 3; base = 57344;  lognch = 4; }
    else                 { s = 4; base = 122880; lognch = 5; }
    const float* W = s == 0 ? w0 : s == 1 ? w1 : s == 2 ? w2 : s == 3 ? w3 : w4;
    const int K = 32 << lognch;
    int lv = v - base;
    int lane = lv & 31, nt = (lv >> 5) & 7, wn = (lv >> 8) & 1;
    int rest = lv >> 9;
    int kc   = rest & ((1 << lognch) - 1);
    int nblk = rest >> lognch;
    int lg = lane >> 2, lt = lane & 3;
    int col = nblk * 128 + wn * 64 + nt * 8 + lg;
    const float* wr = W + (size_t)col * K + kc * 32 + lt * 2;
    float2 b0 = *(const float2*)wr;
    float2 b1 = *(const float2*)(wr + 8);
    float2 b2 = *(const float2*)(wr + 16);
    float2 b3 = *(const float2*)(wr + 24);
    uint4 o;
    o.x = h2pack(b0.x, b0.y);
    o.y = h2pack(b1.x, b1.y);
    o.z = h2pack(b2.x, b2.y);
    o.w = h2pack(b3.x, b3.y);
    out[v] = o;
}

// ---------------------------------------------------------------------------
// GEMM core: CTA 128x128, 4 warps (2m x 2n of 64x64), BK=32,
// 4-stage cp.async pipeline.
// ---------------------------------------------------------------------------
struct GemmCtx {
    float c[4][8][4];
    int lane, wm, wn, lg, lt;
};

__device__ __forceinline__ void gemm_fetch(
    const uint4* __restrict__ Ag, const uint4* __restrict__ Bg,
    uint32_t sb, int stage, int ch, int tid)
{
    const uint4* as = Ag + (size_t)ch * 512 + tid;
    const uint4* bs = Bg + (size_t)ch * 512 + tid;
    uint32_t da = sb + (uint32_t)(stage * 1024 + tid) * 16;
#pragma unroll
    for (int i = 0; i < 4; i++) {
        asm volatile("cp.async.cg.shared.global [%0], [%1], 16;" :: "r"(da + i * 2048), "l"(as + i * 128));
        asm volatile("cp.async.cg.shared.global [%0], [%1], 16;" :: "r"(da + 8192 + i * 2048), "l"(bs + i * 128));
    }
}

__device__ __forceinline__ void gemm_core(
    const uint4* __restrict__ Ag, const uint4* __restrict__ Bg,
    int nch, uint4* sm, GemmCtx& gc, int tid)
{
    const uint32_t sb = smem_u32(sm);
#pragma unroll
    for (int mt = 0; mt < 4; mt++)
#pragma unroll
        for (int nt = 0; nt < 8; nt++)
#pragma unroll
            for (int j = 0; j < 4; j++) gc.c[mt][nt][j] = 0.f;

    int fetch = 0;
#pragma unroll
    for (int p = 0; p < NSTAGE - 1; p++) {
        if (fetch < nch) gemm_fetch(Ag, Bg, sb, p, fetch, tid);
        asm volatile("cp.async.commit_group;");
        fetch++;
    }

    int cs = 0, fs = NSTAGE - 1;
    for (int ch = 0; ch < nch; ch++) {
        asm volatile("cp.async.wait_group %0;" :: "n"(NSTAGE - 2));
        __syncthreads();
        const uint4* As = sm + cs * 1024;
        const uint4* Bs = As + 512;

        uint4 aq[8], bq[8];
#pragma unroll
        for (int f = 0; f < 8; f++) aq[f] = As[(gc.wm * 8 + f) * 32 + gc.lane];
#pragma unroll
        for (int nt = 0; nt < 8; nt++) bq[nt] = Bs[(gc.wn * 8 + nt) * 32 + gc.lane];

#pragma unroll
        for (int ks = 0; ks < 2; ks++)
#pragma unroll
            for (int mt = 0; mt < 4; mt++) {
                const uint4& a = aq[mt * 2 + ks];
#pragma unroll
                for (int nt = 0; nt < 8; nt++) {
                    uint32_t b0 = ks ? bq[nt].z : bq[nt].x;
                    uint32_t b1 = ks ? bq[nt].w : bq[nt].y;
                    mma_f16(gc.c[mt][nt], a, b0, b1);
                }
            }

        if (fetch < nch) gemm_fetch(Ag, Bg, sb, fs, fetch, tid);
        asm volatile("cp.async.commit_group;");
        fetch++;
        cs = (cs + 1) & (NSTAGE - 1);
        fs = (fs + 1) & (NSTAGE - 1);
    }
}

__device__ __forceinline__ void gemm_stats(const GemmCtx& gc, int bn, float* __restrict__ st)
{
#pragma unroll
    for (int nt = 0; nt < 8; nt++) {
        float s0 = 0.f, s1 = 0.f, q0 = 0.f, q1 = 0.f;
#pragma unroll
        for (int mt = 0; mt < 4; mt++) {
            float e0 = gc.c[mt][nt][0], e1 = gc.c[mt][nt][1];
            float e2 = gc.c[mt][nt][2], e3 = gc.c[mt][nt][3];
            s0 += e0 + e2; s1 += e1 + e3;
            q0 += e0 * e0 + e2 * e2;
            q1 += e1 * e1 + e3 * e3;
        }
#pragma unroll
        for (int off = 4; off < 32; off <<= 1) {
            s0 += __shfl_xor_sync(0xffffffffu, s0, off);
            s1 += __shfl_xor_sync(0xffffffffu, s1, off);
            q0 += __shfl_xor_sync(0xffffffffu, q0, off);
            q1 += __shfl_xor_sync(0xffffffffu, q1, off);
        }
        if (gc.lane < 4) {
            int col = bn * 128 + gc.wn * 64 + nt * 8 + gc.lane * 2;
            atomicAdd(&st[col],            s0);
            atomicAdd(&st[col + 1],        s1);
            atomicAdd(&st[NOUT + col],     q0);
            atomicAdd(&st[NOUT + col + 1], q1);
        }
    }
}

// ---------------------------------------------------------------------------
// All 4 branch GEMMs in one launch (longest stage dispatched first). Y fp16.
// ---------------------------------------------------------------------------
__global__ __launch_bounds__(128, 2) void gemm_branch_kernel(
    const uint4* __restrict__ A, const uint4* __restrict__ B,
    __half* __restrict__ Yh, float* __restrict__ stats)
{
    extern __shared__ uint4 sm[];
    const int tid = threadIdx.x;
    const int s = 3 - blockIdx.z;    // K=512 stage first for load balance
    const int nchs[4]  = {2, 4, 8, 16};
    const int aoff[4]  = {0, 65536, 196608, 458752};
    const int woff[4]  = {0, 8192, 24576, 57344};
    const int nch = nchs[s];
    const int bn = blockIdx.x, bm = blockIdx.y;

    GemmCtx gc;
    gc.lane = tid & 31;
    int wid = tid >> 5;
    gc.wm = wid & 1; gc.wn = wid >> 1;
    gc.lg = gc.lane >> 2; gc.lt = gc.lane & 3;

    gemm_core(A + (size_t)aoff[s] + (size_t)bm * nch * 512,
              B + (size_t)woff[s] + (size_t)bn * nch * 512,
              nch, sm, gc, tid);

    __half* Y = Yh + (size_t)s * MROWS * NOUT;
    const int rowbase = bm * 128 + gc.wm * 64 + gc.lg;
    const int colbase = bn * 128 + gc.wn * 64 + gc.lt * 2;
#pragma unroll
    for (int mt = 0; mt < 4; mt++) {
        const int r0 = rowbase + mt * 16;
#pragma unroll
        for (int nt = 0; nt < 8; nt++) {
            const int cc = colbase + nt * 8;
            *(uint32_t*)&Y[(size_t)r0 * NOUT + cc]       = h2pack(gc.c[mt][nt][0], gc.c[mt][nt][1]);
            *(uint32_t*)&Y[(size_t)(r0 + 8) * NOUT + cc] = h2pack(gc.c[mt][nt][2], gc.c[mt][nt][3]);
        }
    }
    gemm_stats(gc, bn, stats + (size_t)s * 2048);
}

// ---------------------------------------------------------------------------
// Final GEMM (K=1024), fp16 Y output + fused stats. bm_base selects M half.
// ---------------------------------------------------------------------------
__global__ __launch_bounds__(128, 2) void gemm_final_kernel(
    const uint4* __restrict__ A, const uint4* __restrict__ B,
    __half* __restrict__ Yh, float* __restrict__ st, int bm_base)
{
    extern __shared__ uint4 sm[];
    const int tid = threadIdx.x;
    const int bn = blockIdx.x, bm = bm_base + blockIdx.y;
    const int nch = 32;

    GemmCtx gc;
    gc.lane = tid & 31;
    int wid = tid >> 5;
    gc.wm = wid & 1; gc.wn = wid >> 1;
    gc.lg = gc.lane >> 2; gc.lt = gc.lane & 3;

    gemm_core(A + (size_t)bm * nch * 512, B + (size_t)bn * nch * 512, nch, sm, gc, tid);

    const int rowbase = bm * 128 + gc.wm * 64 + gc.lg;
    const int colbase = bn * 128 + gc.wn * 64 + gc.lt * 2;
#pragma unroll
    for (int mt = 0; mt < 4; mt++) {
        const int r0 = rowbase + mt * 16;
#pragma unroll
        for (int nt = 0; nt < 8; nt++) {
            const int cc = colbase + nt * 8;
            *(uint32_t*)&Yh[(size_t)r0 * NOUT + cc]       = h2pack(gc.c[mt][nt][0], gc.c[mt][nt][1]);
            *(uint32_t*)&Yh[(size_t)(r0 + 8) * NOUT + cc] = h2pack(gc.c[mt][nt][2], gc.c[mt][nt][3]);
        }
    }
    gemm_stats(gc, bn, st);
}

// ---------------------------------------------------------------------------
// Fused: finalize BN stages 0-3 + acc = f4 + sum leaky(norm(y_s)) -> fp16
// fragment-major stage-5 A operand. mblk_base selects M half.
// Grid 1024 (32 mblk x 32 kc) per half, block 256.
// ---------------------------------------------------------------------------
__global__ __launch_bounds__(256) void norm_acc4_kernel(
    const __half* __restrict__ yh,
    const float* __restrict__ f4,
    const float* __restrict__ stats,
    const float* __restrict__ g0, const float* __restrict__ g1,
    const float* __restrict__ g2, const float* __restrict__ g3,
    const float* __restrict__ be0, const float* __restrict__ be1,
    const float* __restrict__ be2, const float* __restrict__ be3,
    uint4* __restrict__ accf, int mblk_base)
{
    __shared__ float smt[128 * 36];
    __shared__ float scsh[4][2][32];
    const int mblk = mblk_base + (blockIdx.x >> 5);
    const int kc   = blockIdx.x & 31;
    const int tid  = threadIdx.x;

    if (tid < 128) {
        int s = tid >> 5, lc = tid & 31;
        const float* st = stats + s * 2048;
        int ch = kc * 32 + lc;
        const float* gp  = s == 0 ? g0  : s == 1 ? g1  : s == 2 ? g2  : g3;
        const float* bep = s == 0 ? be0 : s == 1 ? be1 : s == 2 ? be2 : be3;
        const float inv = 1.0f / (float)MROWS;
        float mean = st[ch] * inv;
        float var  = st[NOUT + ch] * inv - mean * mean;
        float sc   = rsqrtf(var + EPSV) * gp[ch];
        scsh[s][0][lc] = sc;
        scsh[s][1][lc] = bep[ch] - mean * sc;
    }
    __syncthreads();

#pragma unroll
    for (int i = 0; i < 4; i++) {
        int v = tid + 256 * i;          // 0..1023 quads of the 128x32 chunk
        int r = v >> 3, cq = (v & 7) * 4;
        size_t off = ((size_t)(mblk * 128 + r)) * NOUT + kc * 32 + cq;
        float4 a = *(const float4*)(f4 + off);
#pragma unroll
        for (int s = 0; s < 4; s++) {
            uint2 raw = __ldcs((const uint2*)(yh + (size_t)s * MROWS * NOUT + off));
            float4 y = h4unpack(raw);
            a.x += leaky(y.x * scsh[s][0][cq + 0] + scsh[s][1][cq + 0]);
            a.y += leaky(y.y * scsh[s][0][cq + 1] + scsh[s][1][cq + 1]);
            a.z += leaky(y.z * scsh[s][0][cq + 2] + scsh[s][1][cq + 2]);
            a.w += leaky(y.w * scsh[s][0][cq + 3] + scsh[s][1][cq + 3]);
        }
        *(float4*)&smt[r * 36 + cq] = a;
    }
    __syncthreads();

#pragma unroll
    for (int i = 0; i < 2; i++) {
        int o = tid + 256 * i;          // 0..511 fragment uint4 in this chunk
        int lane = o & 31, f = (o >> 5) & 7, wm = (o >> 8) & 1;
        int mt = f >> 1, ks = f & 1;
        int lg = lane >> 2, lt = lane & 3;
        int r0 = wm * 64 + mt * 16 + lg;
        int c0 = ks * 16 + lt * 2;
        uint4 w;
        w.x = h2pack(smt[r0 * 36 + c0],       smt[r0 * 36 + c0 + 1]);
        w.y = h2pack(smt[(r0 + 8) * 36 + c0], smt[(r0 + 8) * 36 + c0 + 1]);
        w.z = h2pack(smt[r0 * 36 + c0 + 8],       smt[r0 * 36 + c0 + 9]);
        w.w = h2pack(smt[(r0 + 8) * 36 + c0 + 8], smt[(r0 + 8) * 36 + c0 + 9]);
        accf[((size_t)(mblk * 32 + kc)) * 512 + o] = w;
    }
}

// ---------------------------------------------------------------------------
// Finalize stage-4 stats into scale/shift (in place; 4 blocks, tiny)
// ---------------------------------------------------------------------------
__global__ void finalize_stats_kernel(float* __restrict__ st,
                                      const float* __restrict__ g,
                                      const float* __restrict__ be)
{
    int c = blockIdx.x * blockDim.x + threadIdx.x;
    if (c >= NOUT) return;
    const float inv = 1.0f / (float)MROWS;
    float mean = st[c] * inv;
    float var  = st[NOUT + c] * inv - mean * mean;
    float sc   = rsqrtf(var + EPSV) * g[c];
    st[c]        = sc;
    st[NOUT + c] = be[c] - mean * sc;
}

// out = leaky(y * sc + sh) + f4   (streaming store; out never re-read)
__global__ void norm_final_kernel(const __half* __restrict__ yh,
                                  const float* __restrict__ st,
                                  const float4* __restrict__ f4,
                                  float4* __restrict__ out)
{
    int i = blockIdx.x * blockDim.x + threadIdx.x;
    int c4 = i & 255;
    float4 sc = ((const float4*)st)[c4];
    float4 sh = ((const float4*)(st + NOUT))[c4];
    float4 y = h4unpack(__ldcs((const uint2*)yh + i));
    float4 r = f4[i];
    float4 o;
    o.x = leaky(y.x * sc.x + sh.x) + r.x;
    o.y = leaky(y.y * sc.y + sh.y) + r.y;
    o.z = leaky(y.z * sc.z + sh.z) + r.z;
    o.w = leaky(y.w * sc.w + sh.w) + r.w;
    __stcs(out + i, o);
}

// ---------------------------------------------------------------------------
// Host launcher
// ---------------------------------------------------------------------------
extern "C" void kernel_launch(void* const* d_in, const int* in_sizes, int n_in,
                              void* d_out, int out_size)
{
    (void)in_sizes; (void)n_in; (void)out_size;

    const float* f[5];
    for (int i = 0; i < 5; i++) f[i] = (const float*)d_in[1 + i];
    const int* FPS[4];
    for (int i = 0; i < 4; i++) FPS[i] = (const int*)d_in[6 + i];

    const float* w[5]; const float* gam[5]; const float* bet[5];
    for (int i = 0; i < 5; i++) {
        w[i]   = (const float*)d_in[10 + 4 * i + 0];
        gam[i] = (const float*)d_in[10 + 4 * i + 2];
        bet[i] = (const float*)d_in[10 + 4 * i + 3];
    }

    float* out = (float*)d_out;

    float *stats;
    __half *ybufh, *yfh;
    uint4 *abuf, *accf, *wbuf;
    int   *rows;
    cudaGetSymbolAddress((void**)&ybufh, g_ybufh);
    cudaGetSymbolAddress((void**)&yfh,   g_yfh);
    cudaGetSymbolAddress((void**)&abuf,  g_abuf);
    cudaGetSymbolAddress((void**)&accf,  g_accf);
    cudaGetSymbolAddress((void**)&wbuf,  g_wbuf);
    cudaGetSymbolAddress((void**)&stats, g_stats);
    cudaGetSymbolAddress((void**)&rows,  g_rows);

    if (!g_s2) {
        cudaStreamCreateWithFlags(&g_s2, cudaStreamNonBlocking);
        cudaStreamCreateWithFlags(&g_s3, cudaStreamNonBlocking);
        cudaEventCreateWithFlags(&g_e1, cudaEventDisableTiming);
        cudaEventCreateWithFlags(&g_e2, cudaEventDisableTiming);
        cudaEventCreateWithFlags(&g_e3, cudaEventDisableTiming);
        cudaEventCreateWithFlags(&g_e4, cudaEventDisableTiming);
        cudaEventCreateWithFlags(&g_e6, cudaEventDisableTiming);
        cudaFuncSetAttribute(gemm_branch_kernel,
                             cudaFuncAttributeMaxDynamicSharedMemorySize, GEMM_SMEM);
        cudaFuncSetAttribute(gemm_final_kernel,
                             cudaFuncAttributeMaxDynamicSharedMemorySize, GEMM_SMEM);
    }

    // Fork point
    cudaEventRecord(g_e1, 0);

    // Stream 2: pass-through copies via COPY ENGINES (no SM occupancy)
    cudaStreamWaitEvent(g_s2, g_e1, 0);
    for (int i = 0; i < 4; i++) {
        cudaMemcpyAsync(out + (size_t)i * CHUNK, f[i],
                        (size_t)CHUNK * sizeof(float),
                        cudaMemcpyDeviceToDevice, g_s2);
    }
    cudaEventRecord(g_e2, g_s2);

    // Stream 3: weight conversion
    cudaStreamWaitEvent(g_s3, g_e1, 0);
    convW_kernel<<<992, 256, 0, g_s3>>>(w[0], w[1], w[2], w[3], w[4], wbuf);
    cudaEventRecord(g_e3, g_s3);

    // Main chain
    cudaMemsetAsync(stats, 0, 5 * 2 * NOUT * sizeof(float), 0);
    idx_kernel<<<MROWS / 256, 256>>>(FPS[0], FPS[1], FPS[2], FPS[3], rows);
    gatherA_kernel<<<3840, 256>>>(f[0], f[1], f[2], f[3], rows, abuf);
    cudaStreamWaitEvent(0, g_e3, 0);

    gemm_branch_kernel<<<dim3(8, 64, 4), 128, GEMM_SMEM>>>(abuf, wbuf, ybufh, stats);

    // --- Pipelined tail: norm_acc4 (memory-bound) overlaps gemm_final
    //     (tensor-bound) on the other M half.
    // main:  na_lo ─ e4 ─ na_hi ──────── gf_hi ─ (wait e6)
    // s3:            └─ wait e4 ─ gf_lo ─ e6
    norm_acc4_kernel<<<1024, 256>>>(
        ybufh, f[4], stats,
        gam[0], gam[1], gam[2], gam[3],
        bet[0], bet[1], bet[2], bet[3],
        accf, 0);
    cudaEventRecord(g_e4, 0);

    cudaStreamWaitEvent(g_s3, g_e4, 0);
    gemm_final_kernel<<<dim3(8, 32), 128, GEMM_SMEM, g_s3>>>(
        accf, wbuf + 122880, yfh, stats + 4 * 2048, 0);
    cudaEventRecord(g_e6, g_s3);

    norm_acc4_kernel<<<1024, 256>>>(
        ybufh, f[4], stats,
        gam[0], gam[1], gam[2], gam[3],
        bet[0], bet[1], bet[2], bet[3],
        accf, 32);

    gemm_final_kernel<<<dim3(8, 32), 128, GEMM_SMEM>>>(
        accf, wbuf + 122880, yfh, stats + 4 * 2048, 32);

    cudaStreamWaitEvent(0, g_e6, 0);
    finalize_stats_kernel<<<4, 256>>>(stats + 4 * 2048, gam[4], bet[4]);

    norm_final_kernel<<<CHUNK / 4 / 256, 256>>>(
        yfh, stats + 4 * 2048,
        (const float4*)f[4], (float4*)(out + (size_t)4 * CHUNK));

    // Join the copy fork
    cudaStreamWaitEvent(0, g_e2, 0);
}

// round 17
// speedup vs baseline: 1.0104x; 1.0104x over previous
#include <cuda_runtime.h>
#include <cuda_fp16.h>
#include <cstdint>
#include <cstddef>

#define MROWS   8192
#define NOUT    1024
#define CHUNK   8388608
#define SLOPE   0.2f
#define EPSV    1e-5f

#define NSTAGE  4
#define GEMM_SMEM (NSTAGE * 1024 * 16)   // 64 KB dynamic smem per CTA

// ---------------------------------------------------------------------------
// Scratch (device globals)
// ---------------------------------------------------------------------------
__device__ __half g_ybufh[4u * MROWS * NOUT]; // 64 MB: branch GEMM outputs (fp16)
__device__ __half g_yfh[MROWS * NOUT];        // 16 MB: final GEMM output (fp16)
__device__ uint4  g_abuf[983040];             // branch A' fp16 fragment-major
__device__ uint4  g_accf[1048576];            // stage-5 A' fp16 fragment-major
__device__ uint4  g_wbuf[253952];             // W' fp16 fragment-major (all 5)
__device__ int    g_rows[4 * MROWS];
__device__ float  g_stats[5 * 2 * NOUT];      // raw [sum|sumsq] -> [scale|shift]

// Cached side-streams/events (infra only; captured work identical per call)
static cudaStream_t g_s2 = nullptr, g_s3 = nullptr;
static cudaEvent_t  g_e1 = nullptr, g_e2 = nullptr, g_e3 = nullptr;
static cudaEvent_t  g_e4 = nullptr, g_e6 = nullptr;

// ---------------------------------------------------------------------------
// Helpers
// ---------------------------------------------------------------------------
__device__ __forceinline__ uint32_t smem_u32(const void* p) {
    uint32_t a;
    asm("{ .reg .u64 t; cvta.to.shared.u64 t, %1; cvt.u32.u64 %0, t; }" : "=r"(a) : "l"(p));
    return a;
}
__device__ __forceinline__ uint32_t h2pack(float a, float b) {
    __half2 h = __floats2half2_rn(a, b);
    return *(uint32_t*)&h;
}
__device__ __forceinline__ float4 h4unpack(uint2 v) {
    __half2 a = *(__half2*)&v.x, b = *(__half2*)&v.y;
    float2 fa = __half22float2(a), fb = __half22float2(b);
    return make_float4(fa.x, fa.y, fb.x, fb.y);
}
__device__ __forceinline__ void mma_f16(float c[4], const uint4& a, uint32_t b0, uint32_t b1)
{
    asm volatile(
        "mma.sync.aligned.m16n8k16.row.col.f32.f16.f16.f32 "
        "{%0,%1,%2,%3}, {%4,%5,%6,%7}, {%8,%9}, {%0,%1,%2,%3};\n"
        : "+f"(c[0]), "+f"(c[1]), "+f"(c[2]), "+f"(c[3])
        : "r"(a.x), "r"(a.y), "r"(a.z), "r"(a.w), "r"(b0), "r"(b1));
}
__device__ __forceinline__ float leaky(float v) { return v >= 0.f ? v : SLOPE * v; }

// ---------------------------------------------------------------------------
// Index chains
// ---------------------------------------------------------------------------
__global__ void idx_kernel(const int* __restrict__ F0, const int* __restrict__ F1,
                           const int* __restrict__ F2, const int* __restrict__ F3,
                           int* __restrict__ rows)
{
    int i = blockIdx.x * blockDim.x + threadIdx.x;
    if (i >= MROWS) return;
    int b  = i >> 7;
    int i3 = F3[i];
    int i2 = F2[(b << 8) + i3];
    int i1 = F1[(b << 9) + i2];
    int i0 = F0[(b << 10) + i1];
    rows[0 * MROWS + i] = (b << 11) + i0;
    rows[1 * MROWS + i] = (b << 10) + i1;
    rows[2 * MROWS + i] = (b << 9)  + i2;
    rows[3 * MROWS + i] = (b << 8)  + i3;
}

// ---------------------------------------------------------------------------
// Gather + fp16-convert branch A operands into m16n8k16 fragment-major layout.
// vbase selects the sub-range (split so stage 3 can be gathered first).
// ---------------------------------------------------------------------------
__global__ void gatherA_kernel(const float* __restrict__ f0, const float* __restrict__ f1,
                               const float* __restrict__ f2, const float* __restrict__ f3,
                               const int* __restrict__ rows, uint4* __restrict__ out,
                               int vbase)
{
    int v = vbase + blockIdx.x * 256 + threadIdx.x;   // 0 .. 983039
    int s, base, lognch;
    if      (v < 65536)  { s = 0; base = 0;      lognch = 1; }
    else if (v < 196608) { s = 1; base = 65536;  lognch = 2; }
    else if (v < 458752) { s = 2; base = 196608; lognch = 3; }
    else                 { s = 3; base = 458752; lognch = 4; }
    const float* X = s == 0 ? f0 : s == 1 ? f1 : s == 2 ? f2 : f3;
    const int K = 32 << lognch;
    int lv = v - base;
    int lane = lv & 31, f = (lv >> 5) & 7, wm = (lv >> 8) & 1;
    int mt = f >> 1, ks = f & 1;
    int rest = lv >> 9;
    int kc   = rest & ((1 << lognch) - 1);
    int mblk = rest >> lognch;
    int lg = lane >> 2, lt = lane & 3;
    int gR = mblk * 128 + wm * 64 + mt * 16 + lg;
    const int* rs = rows + s * MROWS;
    int r0 = rs[gR], r1 = rs[gR + 8];
    int c0 = kc * 32 + ks * 16 + lt * 2;
    const float* p0 = X + (size_t)r0 * K + c0;
    const float* p1 = X + (size_t)r1 * K + c0;
    float2 a0 = *(const float2*)p0,       a1 = *(const float2*)p1;
    float2 a2 = *(const float2*)(p0 + 8), a3 = *(const float2*)(p1 + 8);
    uint4 o;
    o.x = h2pack(a0.x, a0.y);
    o.y = h2pack(a1.x, a1.y);
    o.z = h2pack(a2.x, a2.y);
    o.w = h2pack(a3.x, a3.y);
    out[v] = o;
}

// ---------------------------------------------------------------------------
// Convert all 5 weight matrices into fp16 fragment-major B layout.
// ---------------------------------------------------------------------------
__global__ void convW_kernel(const float* __restrict__ w0, const float* __restrict__ w1,
                             const float* __restrict__ w2, const float* __restrict__ w3,
                             const float* __restrict__ w4, uint4* __restrict__ out)
{
    int v = blockIdx.x * 256 + threadIdx.x;   // 0 .. 253951
    int s, base, lognch;
    if      (v < 8192)   { s = 0; base = 0;      lognch = 1; }
    else if (v < 24576)  { s = 1; base = 8192;   lognch = 2; }
    else if (v < 57344)  { s = 2; base = 24576;  lognch = 3; }
    else if (v < 122880) { s = 3; base = 57344;  lognch = 4; }
    else                 { s = 4; base = 122880; lognch = 5; }
    const float* W = s == 0 ? w0 : s == 1 ? w1 : s == 2 ? w2 : s == 3 ? w3 : w4;
    const int K = 32 << lognch;
    int lv = v - base;
    int lane = lv & 31, nt = (lv >> 5) & 7, wn = (lv >> 8) & 1;
    int rest = lv >> 9;
    int kc   = rest & ((1 << lognch) - 1);
    int nblk = rest >> lognch;
    int lg = lane >> 2, lt = lane & 3;
    int col = nblk * 128 + wn * 64 + nt * 8 + lg;
    const float* wr = W + (size_t)col * K + kc * 32 + lt * 2;
    float2 b0 = *(const float2*)wr;
    float2 b1 = *(const float2*)(wr + 8);
    float2 b2 = *(const float2*)(wr + 16);
    float2 b3 = *(const float2*)(wr + 24);
    uint4 o;
    o.x = h2pack(b0.x, b0.y);
    o.y = h2pack(b1.x, b1.y);
    o.z = h2pack(b2.x, b2.y);
    o.w = h2pack(b3.x, b3.y);
    out[v] = o;
}

// ---------------------------------------------------------------------------
// GEMM core: CTA 128x128, 4 warps (2m x 2n of 64x64), BK=32,
// 4-stage cp.async pipeline.
// ---------------------------------------------------------------------------
struct GemmCtx {
    float c[4][8][4];
    int lane, wm, wn, lg, lt;
};

__device__ __forceinline__ void gemm_fetch(
    const uint4* __restrict__ Ag, const uint4* __restrict__ Bg,
    uint32_t sb, int stage, int ch, int tid)
{
    const uint4* as = Ag + (size_t)ch * 512 + tid;
    const uint4* bs = Bg + (size_t)ch * 512 + tid;
    uint32_t da = sb + (uint32_t)(stage * 1024 + tid) * 16;
#pragma unroll
    for (int i = 0; i < 4; i++) {
        asm volatile("cp.async.cg.shared.global [%0], [%1], 16;" :: "r"(da + i * 2048), "l"(as + i * 128));
        asm volatile("cp.async.cg.shared.global [%0], [%1], 16;" :: "r"(da + 8192 + i * 2048), "l"(bs + i * 128));
    }
}

__device__ __forceinline__ void gemm_core(
    const uint4* __restrict__ Ag, const uint4* __restrict__ Bg,
    int nch, uint4* sm, GemmCtx& gc, int tid)
{
    const uint32_t sb = smem_u32(sm);
#pragma unroll
    for (int mt = 0; mt < 4; mt++)
#pragma unroll
        for (int nt = 0; nt < 8; nt++)
#pragma unroll
            for (int j = 0; j < 4; j++) gc.c[mt][nt][j] = 0.f;

    int fetch = 0;
#pragma unroll
    for (int p = 0; p < NSTAGE - 1; p++) {
        if (fetch < nch) gemm_fetch(Ag, Bg, sb, p, fetch, tid);
        asm volatile("cp.async.commit_group;");
        fetch++;
    }

    int cs = 0, fs = NSTAGE - 1;
    for (int ch = 0; ch < nch; ch++) {
        asm volatile("cp.async.wait_group %0;" :: "n"(NSTAGE - 2));
        __syncthreads();
        const uint4* As = sm + cs * 1024;
        const uint4* Bs = As + 512;

        uint4 aq[8], bq[8];
#pragma unroll
        for (int f = 0; f < 8; f++) aq[f] = As[(gc.wm * 8 + f) * 32 + gc.lane];
#pragma unroll
        for (int nt = 0; nt < 8; nt++) bq[nt] = Bs[(gc.wn * 8 + nt) * 32 + gc.lane];

#pragma unroll
        for (int ks = 0; ks < 2; ks++)
#pragma unroll
            for (int mt = 0; mt < 4; mt++) {
                const uint4& a = aq[mt * 2 + ks];
#pragma unroll
                for (int nt = 0; nt < 8; nt++) {
                    uint32_t b0 = ks ? bq[nt].z : bq[nt].x;
                    uint32_t b1 = ks ? bq[nt].w : bq[nt].y;
                    mma_f16(gc.c[mt][nt], a, b0, b1);
                }
            }

        if (fetch < nch) gemm_fetch(Ag, Bg, sb, fs, fetch, tid);
        asm volatile("cp.async.commit_group;");
        fetch++;
        cs = (cs + 1) & (NSTAGE - 1);
        fs = (fs + 1) & (NSTAGE - 1);
    }
}

__device__ __forceinline__ void gemm_stats(const GemmCtx& gc, int bn, float* __restrict__ st)
{
#pragma unroll
    for (int nt = 0; nt < 8; nt++) {
        float s0 = 0.f, s1 = 0.f, q0 = 0.f, q1 = 0.f;
#pragma unroll
        for (int mt = 0; mt < 4; mt++) {
            float e0 = gc.c[mt][nt][0], e1 = gc.c[mt][nt][1];
            float e2 = gc.c[mt][nt][2], e3 = gc.c[mt][nt][3];
            s0 += e0 + e2; s1 += e1 + e3;
            q0 += e0 * e0 + e2 * e2;
            q1 += e1 * e1 + e3 * e3;
        }
#pragma unroll
        for (int off = 4; off < 32; off <<= 1) {
            s0 += __shfl_xor_sync(0xffffffffu, s0, off);
            s1 += __shfl_xor_sync(0xffffffffu, s1, off);
            q0 += __shfl_xor_sync(0xffffffffu, q0, off);
            q1 += __shfl_xor_sync(0xffffffffu, q1, off);
        }
        if (gc.lane < 4) {
            int col = bn * 128 + gc.wn * 64 + nt * 8 + gc.lane * 2;
            atomicAdd(&st[col],            s0);
            atomicAdd(&st[col + 1],        s1);
            atomicAdd(&st[NOUT + col],     q0);
            atomicAdd(&st[NOUT + col + 1], q1);
        }
    }
}

// ---------------------------------------------------------------------------
// Branch GEMMs. s_fixed >= 0: single stage; s_fixed < 0: s = 2 - blockIdx.z
// (stages 2, 1, 0). Y fp16.
// ---------------------------------------------------------------------------
__global__ __launch_bounds__(128, 2) void gemm_branch_kernel(
    const uint4* __restrict__ A, const uint4* __restrict__ B,
    __half* __restrict__ Yh, float* __restrict__ stats, int s_fixed)
{
    extern __shared__ uint4 sm[];
    const int tid = threadIdx.x;
    const int s = s_fixed >= 0 ? s_fixed : (2 - (int)blockIdx.z);
    const int nchs[4]  = {2, 4, 8, 16};
    const int aoff[4]  = {0, 65536, 196608, 458752};
    const int woff[4]  = {0, 8192, 24576, 57344};
    const int nch = nchs[s];
    const int bn = blockIdx.x, bm = blockIdx.y;

    GemmCtx gc;
    gc.lane = tid & 31;
    int wid = tid >> 5;
    gc.wm = wid & 1; gc.wn = wid >> 1;
    gc.lg = gc.lane >> 2; gc.lt = gc.lane & 3;

    gemm_core(A + (size_t)aoff[s] + (size_t)bm * nch * 512,
              B + (size_t)woff[s] + (size_t)bn * nch * 512,
              nch, sm, gc, tid);

    __half* Y = Yh + (size_t)s * MROWS * NOUT;
    const int rowbase = bm * 128 + gc.wm * 64 + gc.lg;
    const int colbase = bn * 128 + gc.wn * 64 + gc.lt * 2;
#pragma unroll
    for (int mt = 0; mt < 4; mt++) {
        const int r0 = rowbase + mt * 16;
#pragma unroll
        for (int nt = 0; nt < 8; nt++) {
            const int cc = colbase + nt * 8;
            *(uint32_t*)&Y[(size_t)r0 * NOUT + cc]       = h2pack(gc.c[mt][nt][0], gc.c[mt][nt][1]);
            *(uint32_t*)&Y[(size_t)(r0 + 8) * NOUT + cc] = h2pack(gc.c[mt][nt][2], gc.c[mt][nt][3]);
        }
    }
    gemm_stats(gc, bn, stats + (size_t)s * 2048);
}

// ---------------------------------------------------------------------------
// Final GEMM (K=1024), fp16 Y output + fused stats.
// ---------------------------------------------------------------------------
__global__ __launch_bounds__(128, 2) void gemm_final_kernel(
    const uint4* __restrict__ A, const uint4* __restrict__ B,
    __half* __restrict__ Yh, float* __restrict__ st)
{
    extern __shared__ uint4 sm[];
    const int tid = threadIdx.x;
    const int bn = blockIdx.x, bm = blockIdx.y;
    const int nch = 32;

    GemmCtx gc;
    gc.lane = tid & 31;
    int wid = tid >> 5;
    gc.wm = wid & 1; gc.wn = wid >> 1;
    gc.lg = gc.lane >> 2; gc.lt = gc.lane & 3;

    gemm_core(A + (size_t)bm * nch * 512, B + (size_t)bn * nch * 512, nch, sm, gc, tid);

    const int rowbase = bm * 128 + gc.wm * 64 + gc.lg;
    const int colbase = bn * 128 + gc.wn * 64 + gc.lt * 2;
#pragma unroll
    for (int mt = 0; mt < 4; mt++) {
        const int r0 = rowbase + mt * 16;
#pragma unroll
        for (int nt = 0; nt < 8; nt++) {
            const int cc = colbase + nt * 8;
            *(uint32_t*)&Yh[(size_t)r0 * NOUT + cc]       = h2pack(gc.c[mt][nt][0], gc.c[mt][nt][1]);
            *(uint32_t*)&Yh[(size_t)(r0 + 8) * NOUT + cc] = h2pack(gc.c[mt][nt][2], gc.c[mt][nt][3]);
        }
    }
    gemm_stats(gc, bn, st);
}

// ---------------------------------------------------------------------------
// Fused: finalize BN stages 0-3 + acc = f4 + sum leaky(norm(y_s)) -> fp16
// fragment-major stage-5 A operand. Grid 2048 (64 mblk x 32 kc), block 256.
// ---------------------------------------------------------------------------
__global__ __launch_bounds__(256) void norm_acc4_kernel(
    const __half* __restrict__ yh,
    const float* __restrict__ f4,
    const float* __restrict__ stats,
    const float* __restrict__ g0, const float* __restrict__ g1,
    const float* __restrict__ g2, const float* __restrict__ g3,
    const float* __restrict__ be0, const float* __restrict__ be1,
    const float* __restrict__ be2, const float* __restrict__ be3,
    uint4* __restrict__ accf)
{
    __shared__ float smt[128 * 36];
    __shared__ float scsh[4][2][32];
    const int mblk = blockIdx.x >> 5;
    const int kc   = blockIdx.x & 31;
    const int tid  = threadIdx.x;

    if (tid < 128) {
        int s = tid >> 5, lc = tid & 31;
        const float* st = stats + s * 2048;
        int ch = kc * 32 + lc;
        const float* gp  = s == 0 ? g0  : s == 1 ? g1  : s == 2 ? g2  : g3;
        const float* bep = s == 0 ? be0 : s == 1 ? be1 : s == 2 ? be2 : be3;
        const float inv = 1.0f / (float)MROWS;
        float mean = st[ch] * inv;
        float var  = st[NOUT + ch] * inv - mean * mean;
        float sc   = rsqrtf(var + EPSV) * gp[ch];
        scsh[s][0][lc] = sc;
        scsh[s][1][lc] = bep[ch] - mean * sc;
    }
    __syncthreads();

#pragma unroll
    for (int i = 0; i < 4; i++) {
        int v = tid + 256 * i;          // 0..1023 quads of the 128x32 chunk
        int r = v >> 3, cq = (v & 7) * 4;
        size_t off = ((size_t)(mblk * 128 + r)) * NOUT + kc * 32 + cq;
        float4 a = *(const float4*)(f4 + off);
#pragma unroll
        for (int s = 0; s < 4; s++) {
            uint2 raw = __ldcs((const uint2*)(yh + (size_t)s * MROWS * NOUT + off));
            float4 y = h4unpack(raw);
            a.x += leaky(y.x * scsh[s][0][cq + 0] + scsh[s][1][cq + 0]);
            a.y += leaky(y.y * scsh[s][0][cq + 1] + scsh[s][1][cq + 1]);
            a.z += leaky(y.z * scsh[s][0][cq + 2] + scsh[s][1][cq + 2]);
            a.w += leaky(y.w * scsh[s][0][cq + 3] + scsh[s][1][cq + 3]);
        }
        *(float4*)&smt[r * 36 + cq] = a;
    }
    __syncthreads();

#pragma unroll
    for (int i = 0; i < 2; i++) {
        int o = tid + 256 * i;          // 0..511 fragment uint4 in this chunk
        int lane = o & 31, f = (o >> 5) & 7, wm = (o >> 8) & 1;
        int mt = f >> 1, ks = f & 1;
        int lg = lane >> 2, lt = lane & 3;
        int r0 = wm * 64 + mt * 16 + lg;
        int c0 = ks * 16 + lt * 2;
        uint4 w;
        w.x = h2pack(smt[r0 * 36 + c0],       smt[r0 * 36 + c0 + 1]);
        w.y = h2pack(smt[(r0 + 8) * 36 + c0], smt[(r0 + 8) * 36 + c0 + 1]);
        w.z = h2pack(smt[r0 * 36 + c0 + 8],       smt[r0 * 36 + c0 + 9]);
        w.w = h2pack(smt[(r0 + 8) * 36 + c0 + 8], smt[(r0 + 8) * 36 + c0 + 9]);
        accf[((size_t)(mblk * 32 + kc)) * 512 + o] = w;
    }
}

// ---------------------------------------------------------------------------
// Finalize stage-4 stats into scale/shift (in place; 4 blocks, tiny)
// ---------------------------------------------------------------------------
__global__ void finalize_stats_kernel(float* __restrict__ st,
                                      const float* __restrict__ g,
                                      const float* __restrict__ be)
{
    int c = blockIdx.x * blockDim.x + threadIdx.x;
    if (c >= NOUT) return;
    const float inv = 1.0f / (float)MROWS;
    float mean = st[c] * inv;
    float var  = st[NOUT + c] * inv - mean * mean;
    float sc   = rsqrtf(var + EPSV) * g[c];
    st[c]        = sc;
    st[NOUT + c] = be[c] - mean * sc;
}

// out = leaky(y * sc + sh) + f4   (streaming store; out never re-read)
__global__ void norm_final_kernel(const __half* __restrict__ yh,
                                  const float* __restrict__ st,
                                  const float4* __restrict__ f4,
                                  float4* __restrict__ out)
{
    int i = blockIdx.x * blockDim.x + threadIdx.x;
    int c4 = i & 255;
    float4 sc = ((const float4*)st)[c4];
    float4 sh = ((const float4*)(st + NOUT))[c4];
    float4 y = h4unpack(__ldcs((const uint2*)yh + i));
    float4 r = f4[i];
    float4 o;
    o.x = leaky(y.x * sc.x + sh.x) + r.x;
    o.y = leaky(y.y * sc.y + sh.y) + r.y;
    o.z = leaky(y.z * sc.z + sh.z) + r.z;
    o.w = leaky(y.w * sc.w + sh.w) + r.w;
    __stcs(out + i, o);
}

// ---------------------------------------------------------------------------
// Host launcher
// ---------------------------------------------------------------------------
extern "C" void kernel_launch(void* const* d_in, const int* in_sizes, int n_in,
                              void* d_out, int out_size)
{
    (void)in_sizes; (void)n_in; (void)out_size;

    const float* f[5];
    for (int i = 0; i < 5; i++) f[i] = (const float*)d_in[1 + i];
    const int* FPS[4];
    for (int i = 0; i < 4; i++) FPS[i] = (const int*)d_in[6 + i];

    const float* w[5]; const float* gam[5]; const float* bet[5];
    for (int i = 0; i < 5; i++) {
        w[i]   = (const float*)d_in[10 + 4 * i + 0];
        gam[i] = (const float*)d_in[10 + 4 * i + 2];
        bet[i] = (const float*)d_in[10 + 4 * i + 3];
    }

    float* out = (float*)d_out;

    float *stats;
    __half *ybufh, *yfh;
    uint4 *abuf, *accf, *wbuf;
    int   *rows;
    cudaGetSymbolAddress((void**)&ybufh, g_ybufh);
    cudaGetSymbolAddress((void**)&yfh,   g_yfh);
    cudaGetSymbolAddress((void**)&abuf,  g_abuf);
    cudaGetSymbolAddress((void**)&accf,  g_accf);
    cudaGetSymbolAddress((void**)&wbuf,  g_wbuf);
    cudaGetSymbolAddress((void**)&stats, g_stats);
    cudaGetSymbolAddress((void**)&rows,  g_rows);

    if (!g_s2) {
        cudaStreamCreateWithFlags(&g_s2, cudaStreamNonBlocking);
        cudaStreamCreateWithFlags(&g_s3, cudaStreamNonBlocking);
        cudaEventCreateWithFlags(&g_e1, cudaEventDisableTiming);
        cudaEventCreateWithFlags(&g_e2, cudaEventDisableTiming);
        cudaEventCreateWithFlags(&g_e3, cudaEventDisableTiming);
        cudaEventCreateWithFlags(&g_e4, cudaEventDisableTiming);
        cudaEventCreateWithFlags(&g_e6, cudaEventDisableTiming);
        cudaFuncSetAttribute(gemm_branch_kernel,
                             cudaFuncAttributeMaxDynamicSharedMemorySize, GEMM_SMEM);
        cudaFuncSetAttribute(gemm_final_kernel,
                             cudaFuncAttributeMaxDynamicSharedMemorySize, GEMM_SMEM);
    }

    // Fork point
    cudaEventRecord(g_e1, 0);

    // Stream 2: pass-through copies via COPY ENGINES (no SM occupancy)
    cudaStreamWaitEvent(g_s2, g_e1, 0);
    for (int i = 0; i < 4; i++) {
        cudaMemcpyAsync(out + (size_t)i * CHUNK, f[i],
                        (size_t)CHUNK * sizeof(float),
                        cudaMemcpyDeviceToDevice, g_s2);
    }
    cudaEventRecord(g_e2, g_s2);

    // Stream 3: weight conversion (needed before any GEMM)
    cudaStreamWaitEvent(g_s3, g_e1, 0);
    convW_kernel<<<992, 256, 0, g_s3>>>(w[0], w[1], w[2], w[3], w[4], wbuf);
    cudaEventRecord(g_e3, g_s3);

    // Main chain
    cudaMemsetAsync(stats, 0, 5 * 2 * NOUT * sizeof(float), 0);
    idx_kernel<<<MROWS / 256, 256>>>(FPS[0], FPS[1], FPS[2], FPS[3], rows);

    // Gather stage 3's A first (v in [458752, 983040): 2048 blocks)
    gatherA_kernel<<<2048, 256>>>(f[0], f[1], f[2], f[3], rows, abuf, 458752);
    cudaEventRecord(g_e4, 0);

    // Stage-3 GEMM (K=512, 53% of branch FLOPs) on stream 3; overlaps the
    // remaining gather below.
    cudaStreamWaitEvent(g_s3, g_e4, 0);   // after its A gather (e3 ordered before on s3)
    gemm_branch_kernel<<<dim3(8, 64, 1), 128, GEMM_SMEM, g_s3>>>(
        abuf, wbuf, ybufh, stats, 3);
    cudaEventRecord(g_e6, g_s3);

    // Gather stages 0-2 (v in [0, 458752): 1792 blocks), then their GEMMs.
    gatherA_kernel<<<1792, 256>>>(f[0], f[1], f[2], f[3], rows, abuf, 0);
    cudaStreamWaitEvent(0, g_e3, 0);      // weights ready
    gemm_branch_kernel<<<dim3(8, 64, 3), 128, GEMM_SMEM>>>(
        abuf, wbuf, ybufh, stats, -1);

    // Join stage-3 GEMM before consuming its Y / stats.
    cudaStreamWaitEvent(0, g_e6, 0);

    norm_acc4_kernel<<<2048, 256>>>(
        ybufh, f[4], stats,
        gam[0], gam[1], gam[2], gam[3],
        bet[0], bet[1], bet[2], bet[3],
        accf);

    gemm_final_kernel<<<dim3(8, 64), 128, GEMM_SMEM>>>(accf, wbuf + 122880, yfh, stats + 4 * 2048);

    finalize_stats_kernel<<<4, 256>>>(stats + 4 * 2048, gam[4], bet[4]);

    norm_final_kernel<<<CHUNK / 4 / 256, 256>>>(
        yfh, stats + 4 * 2048,
        (const float4*)f[4], (float4*)(out + (size_t)4 * CHUNK));

    // Join the copy fork
    cudaStreamWaitEvent(0, g_e2, 0);
}